// round 1
// baseline (speedup 1.0000x reference)
#include <cuda_runtime.h>
#include <math.h>

static constexpr int N_IN  = 8192;
static constexpr int N_HID = 8192;
static constexpr int N_OUT = 1024;
static constexpr int NIN   = 8192;   // inner dim for both layers

// Scratch (no allocations allowed)
__device__ float g_z[N_IN];        // layer-1 input after exp
__device__ float g_hidden[N_HID];  // layer-1 output / layer-2 input
__device__ float g_Zsum, g_zmin, g_zmax;
__device__ int   g_jlast;

// ---------------------------------------------------------------------------
// Stats over the current z vector: sum, min, max, last index of max
// (last-occurrence tie-break matches stable argsort semantics).
// FIRST=true also applies exp(x) and materializes g_z.
// ---------------------------------------------------------------------------
template<bool FIRST>
__global__ void __launch_bounds__(1024) stats_kernel(const float* __restrict__ x)
{
    const int tid = threadIdx.x;
    float sum = 0.f, mn = INFINITY, mx = -INFINITY;
    int jm = -1;
    #pragma unroll
    for (int j = tid; j < NIN; j += 1024) {
        float v;
        if (FIRST) { v = expf(x[j]); g_z[j] = v; }
        else       { v = g_hidden[j]; }
        sum += v;
        mn = fminf(mn, v);
        if (v > mx || (v == mx && j > jm)) { mx = v; jm = j; }
    }
    __shared__ float ss[1024], smn[1024], smx[1024];
    __shared__ int   sj[1024];
    ss[tid] = sum; smn[tid] = mn; smx[tid] = mx; sj[tid] = jm;
    __syncthreads();
    for (int off = 512; off > 0; off >>= 1) {
        if (tid < off) {
            ss[tid]  += ss[tid + off];
            smn[tid]  = fminf(smn[tid], smn[tid + off]);
            float v2 = smx[tid + off]; int i2 = sj[tid + off];
            if (v2 > smx[tid] || (v2 == smx[tid] && i2 > sj[tid])) { smx[tid] = v2; sj[tid] = i2; }
        }
        __syncthreads();
    }
    if (tid == 0) { g_Zsum = ss[0]; g_zmin = smn[0]; g_zmax = smx[0]; g_jlast = sj[0]; }
}

// ---------------------------------------------------------------------------
// One block per output neuron: row-sum of W, then the closed-form causal set.
// Common path (Wsum > 1): Wc = Wsum - W[row, jlast], Zc = Zsum - zmax.
// Rare path (Wsum <= 1): cooperative second pass over the row.
// ---------------------------------------------------------------------------
template<bool FIRST>
__global__ void __launch_bounds__(256) row_kernel(const float* __restrict__ W,
                                                  float* __restrict__ out)
{
    const int row = blockIdx.x;
    const int tid = threadIdx.x;
    const float* z = FIRST ? g_z : g_hidden;
    const float4* __restrict__ Wr =
        reinterpret_cast<const float4*>(W + (size_t)row * NIN);

    float acc = 0.f;
    #pragma unroll
    for (int i = tid; i < NIN / 4; i += 256) {
        float4 v = Wr[i];
        acc += (v.x + v.y) + (v.z + v.w);
    }
    #pragma unroll
    for (int o = 16; o > 0; o >>= 1) acc += __shfl_down_sync(0xffffffffu, acc, o);

    __shared__ float swp[8];
    const int wid = tid >> 5, lane = tid & 31;
    if (lane == 0) swp[wid] = acc;
    __syncthreads();

    __shared__ int   s_mode;
    __shared__ float s_tmp, s_Wsum;
    if (tid == 0) {
        float Wsum = 0.f;
        #pragma unroll
        for (int w = 0; w < 8; ++w) Wsum += swp[w];
        const float Zsum = g_Zsum, zmin = g_zmin, zmax = g_zmax;
        const int   jlast = g_jlast;
        const float tmp = Wsum * Zsum / (Wsum - 1.f);
        int mode = 0;
        float result = INFINITY;
        if (Wsum > 1.f) {
            if (zmin <= tmp) {                 // first mismatch at i=0 -> k = n-1
                float Wc = Wsum - W[(size_t)row * NIN + jlast];
                float Zc = Zsum - zmax;
                result = Wc * Zc / (Wc - 1.f);
            }                                  // else: no mismatch -> inf
        } else {
            mode = 2; s_tmp = tmp; s_Wsum = Wsum;
        }
        s_mode = mode;
        if (mode == 0) {
            if (FIRST) g_hidden[row] = result; else out[row] = result;
        }
    }
    __syncthreads();
    if (s_mode != 2) return;

    // ---- rare general path (Wsum <= 1): one cooperative pass over z and W ----
    const float tmp = s_tmp;
    int   cnt = 0;
    float sle = 0.f, wle = 0.f, m = -INFINITY;
    int   jm = -1;
    for (int j = tid; j < NIN; j += 256) {
        float zj = z[j];
        if (zj <= tmp) {
            cnt++;
            sle += zj;
            wle += W[(size_t)row * NIN + j];
            if (zj > m || (zj == m && j > jm)) { m = zj; jm = j; }
        }
    }
    __shared__ float shf[256];
    __shared__ int   shi[256];

    shi[tid] = cnt; __syncthreads();
    for (int o = 128; o > 0; o >>= 1) { if (tid < o) shi[tid] += shi[tid + o]; __syncthreads(); }
    const int c = shi[0]; __syncthreads();

    shf[tid] = sle; __syncthreads();
    for (int o = 128; o > 0; o >>= 1) { if (tid < o) shf[tid] += shf[tid + o]; __syncthreads(); }
    const float S_le = shf[0]; __syncthreads();

    shf[tid] = wle; __syncthreads();
    for (int o = 128; o > 0; o >>= 1) { if (tid < o) shf[tid] += shf[tid + o]; __syncthreads(); }
    const float W_le = shf[0]; __syncthreads();

    shf[tid] = m; shi[tid] = jm; __syncthreads();
    for (int o = 128; o > 0; o >>= 1) {
        if (tid < o) {
            float v2 = shf[tid + o]; int i2 = shi[tid + o];
            if (v2 > shf[tid] || (v2 == shf[tid] && i2 > shi[tid])) { shf[tid] = v2; shi[tid] = i2; }
        }
        __syncthreads();
    }

    if (tid == 0) {
        const float Zsum = g_Zsum, zmax = g_zmax;
        const int   jlast = g_jlast;
        const float Wsum = s_Wsum;
        float result = INFINITY;
        if (c == NIN) {
            // no mismatch -> inf
        } else if (c == 0) {
            // first mismatch at i=0 -> k = n-1
            float Wc = Wsum - W[(size_t)row * NIN + jlast];
            float Zc = Zsum - zmax;
            result = Wc * Zc / (Wc - 1.f);
        } else {
            int k = c - 1;
            if (k != 0) {
                float mval = shf[0]; int jmv = shi[0];
                float Zc = S_le - mval;
                float Wc = W_le - W[(size_t)row * NIN + jmv];
                result = Wc * Zc / (Wc - 1.f);
            }
        }
        if (FIRST) g_hidden[row] = result; else out[row] = result;
    }
}

extern "C" void kernel_launch(void* const* d_in, const int* in_sizes, int n_in,
                              void* d_out, int out_size)
{
    const float* x  = (const float*)d_in[0];
    const float* W1 = (const float*)d_in[1];
    const float* W2 = (const float*)d_in[2];
    float* out = (float*)d_out;

    stats_kernel<true><<<1, 1024>>>(x);            // z = exp(x); stats of z
    row_kernel<true><<<N_HID, 256>>>(W1, out);     // hidden = spiking_layer(z, W1)
    stats_kernel<false><<<1, 1024>>>(nullptr);     // stats of hidden
    row_kernel<false><<<N_OUT, 256>>>(W2, out);    // out = spiking_layer(hidden, W2)
}

// round 2
// speedup vs baseline: 1.0378x; 1.0378x over previous
#include <cuda_runtime.h>
#include <math.h>

static constexpr int NIN   = 8192;   // inner dim for both layers
static constexpr int N_HID = 8192;
static constexpr int N_OUT = 1024;

#define FP_SCALE 268435456.0   // 2^28 fixed-point scale for deterministic sums

// ---------------- scratch (no allocations allowed) ----------------
__device__ float g_z[NIN];         // layer-1 z = exp(x)
__device__ float g_hidden[N_HID];  // layer-1 output
__device__ float g_w2sum[N_OUT];   // precomputed W2 row sums

// stats accumulators (deterministic: integer atomics only)
__device__ unsigned long long gx_sum, gx_maxp;  // maxp = (orderkey<<32)|idx
__device__ unsigned int       gx_minb;
__device__ unsigned long long gh_sum, gh_maxp;
__device__ unsigned int       gh_minb;
__device__ unsigned int       g_ticket;

// order-preserving float<->uint key (handles signs; exact total order)
__device__ __forceinline__ unsigned int fkey(float v) {
    unsigned u = __float_as_uint(v);
    return (u & 0x80000000u) ? ~u : (u | 0x80000000u);
}
__device__ __forceinline__ float fdec(unsigned int k) {
    unsigned u = (k & 0x80000000u) ? (k ^ 0x80000000u) : ~k;
    return __uint_as_float(u);
}

// ---------------------------------------------------------------------------
__global__ void init_kernel() {
    gx_sum = 0; gx_maxp = 0; gx_minb = 0xFFFFFFFFu;
    gh_sum = 0; gh_maxp = 0; gh_minb = 0xFFFFFFFFu;
    g_ticket = 0;
}

// ---------------------------------------------------------------------------
// Stats over z = exp(x): deterministic fixed-point sum, min, max+last-argmax.
// ---------------------------------------------------------------------------
__global__ void __launch_bounds__(256) statsx_kernel(const float* __restrict__ x)
{
    const int tid = threadIdx.x;
    long long lsum = 0;
    unsigned int lmin = 0xFFFFFFFFu;
    unsigned long long lmax = 0;
    for (int j = blockIdx.x * 256 + tid; j < NIN; j += gridDim.x * 256) {
        float v = expf(x[j]);
        g_z[j] = v;
        lsum += __double2ll_rn((double)v * FP_SCALE);
        unsigned k = fkey(v);
        lmin = min(lmin, k);
        lmax = max(lmax, ((unsigned long long)k << 32) | (unsigned)j);
    }
    __shared__ long long ss[256];
    __shared__ unsigned int smn[256];
    __shared__ unsigned long long smx[256];
    ss[tid] = lsum; smn[tid] = lmin; smx[tid] = lmax;
    __syncthreads();
    for (int o = 128; o > 0; o >>= 1) {
        if (tid < o) {
            ss[tid] += ss[tid + o];
            smn[tid] = min(smn[tid], smn[tid + o]);
            smx[tid] = max(smx[tid], smx[tid + o]);
        }
        __syncthreads();
    }
    if (tid == 0) {
        atomicAdd(&gx_sum, (unsigned long long)ss[0]);
        atomicMin(&gx_minb, smn[0]);
        atomicMax(&gx_maxp, smx[0]);
    }
}

// ---------------------------------------------------------------------------
// The big streaming wave: blocks [0,8192) process one W1 row each (layer-1
// closed form -> g_hidden); blocks [8192,9216) compute W2 row sums.
// All 288 MB flows through this one kernel at full bandwidth.
// ---------------------------------------------------------------------------
__global__ void __launch_bounds__(256) big_kernel(const float* __restrict__ W1,
                                                  const float* __restrict__ W2)
{
    const int bid = blockIdx.x;
    const int tid = threadIdx.x;
    const bool isW2 = (bid >= N_HID);
    const float* __restrict__ W = isW2 ? W2 : W1;
    const int row = isW2 ? (bid - N_HID) : bid;
    const float4* __restrict__ Wr =
        reinterpret_cast<const float4*>(W + (size_t)row * NIN);

    float acc = 0.f;
    #pragma unroll
    for (int i = 0; i < NIN / 4 / 256; ++i) {
        float4 v = __ldcs(Wr + tid + i * 256);
        acc += (v.x + v.y) + (v.z + v.w);
    }
    #pragma unroll
    for (int o = 16; o > 0; o >>= 1) acc += __shfl_down_sync(0xffffffffu, acc, o);

    __shared__ float swp[8];
    const int wid = tid >> 5, lane = tid & 31;
    if (lane == 0) swp[wid] = acc;
    __syncthreads();

    if (isW2) {
        if (tid == 0) {
            float Wsum = 0.f;
            #pragma unroll
            for (int w = 0; w < 8; ++w) Wsum += swp[w];
            g_w2sum[row] = Wsum;
        }
        return;
    }

    // ---- layer-1 closed form ----
    __shared__ int   s_mode;
    __shared__ float s_tmp, s_Wsum;
    if (tid == 0) {
        float Wsum = 0.f;
        #pragma unroll
        for (int w = 0; w < 8; ++w) Wsum += swp[w];
        const float Zsum = (float)((double)(long long)gx_sum * (1.0 / FP_SCALE));
        const float zmin = fdec(gx_minb);
        const unsigned long long p = gx_maxp;
        const float zmax = fdec((unsigned)(p >> 32));
        const int jlast = (int)(unsigned)p;
        const float tmp = Wsum * Zsum / (Wsum - 1.f);
        int mode = 0;
        float result = INFINITY;
        if (Wsum > 1.f) {
            if (zmin <= tmp) {                 // first mismatch at i=0 -> k = n-1
                float Wc = Wsum - W[(size_t)row * NIN + jlast];
                float Zc = Zsum - zmax;
                result = Wc * Zc / (Wc - 1.f);
            }                                  // else: no mismatch -> inf
        } else {
            mode = 2; s_tmp = tmp; s_Wsum = Wsum;
        }
        s_mode = mode;
        if (mode == 0) g_hidden[row] = result;
    }
    __syncthreads();
    if (s_mode != 2) return;

    // ---- rare general path (Wsum <= 1): cooperative pass over z and W row ----
    const float tmp = s_tmp;
    int   cnt = 0;
    float sle = 0.f, wle = 0.f, m = -INFINITY;
    int   jm = -1;
    for (int j = tid; j < NIN; j += 256) {
        float zj = g_z[j];
        if (zj <= tmp) {
            cnt++; sle += zj; wle += W[(size_t)row * NIN + j];
            if (zj > m || (zj == m && j > jm)) { m = zj; jm = j; }
        }
    }
    __shared__ float shf[256];
    __shared__ int   shi[256];

    shi[tid] = cnt; __syncthreads();
    for (int o = 128; o > 0; o >>= 1) { if (tid < o) shi[tid] += shi[tid + o]; __syncthreads(); }
    const int c = shi[0]; __syncthreads();

    shf[tid] = sle; __syncthreads();
    for (int o = 128; o > 0; o >>= 1) { if (tid < o) shf[tid] += shf[tid + o]; __syncthreads(); }
    const float S_le = shf[0]; __syncthreads();

    shf[tid] = wle; __syncthreads();
    for (int o = 128; o > 0; o >>= 1) { if (tid < o) shf[tid] += shf[tid + o]; __syncthreads(); }
    const float W_le = shf[0]; __syncthreads();

    shf[tid] = m; shi[tid] = jm; __syncthreads();
    for (int o = 128; o > 0; o >>= 1) {
        if (tid < o) {
            float v2 = shf[tid + o]; int i2 = shi[tid + o];
            if (v2 > shf[tid] || (v2 == shf[tid] && i2 > shi[tid])) { shf[tid] = v2; shi[tid] = i2; }
        }
        __syncthreads();
    }

    if (tid == 0) {
        const float Zsum = (float)((double)(long long)gx_sum * (1.0 / FP_SCALE));
        const unsigned long long p = gx_maxp;
        const float zmax = fdec((unsigned)(p >> 32));
        const int jlast = (int)(unsigned)p;
        const float Wsum = s_Wsum;
        float result = INFINITY;
        if (c == NIN) {
            // no mismatch -> inf
        } else if (c == 0) {
            float Wc = Wsum - W[(size_t)row * NIN + jlast];
            float Zc = Zsum - zmax;
            result = Wc * Zc / (Wc - 1.f);
        } else {
            int k = c - 1;
            if (k != 0) {
                float Zc = S_le - shf[0];
                float Wc = W_le - W[(size_t)row * NIN + shi[0]];
                result = Wc * Zc / (Wc - 1.f);
            }
        }
        g_hidden[row] = result;
    }
}

// ---------------------------------------------------------------------------
// Stats over g_hidden + (last finishing block) the entire layer-2 epilogue:
// 1024 closed-form evaluations using precomputed W2 row sums.
// ---------------------------------------------------------------------------
__global__ void __launch_bounds__(256) statsh_final_kernel(const float* __restrict__ W2,
                                                           float* __restrict__ out)
{
    const int tid = threadIdx.x;
    long long lsum = 0;
    unsigned int lmin = 0xFFFFFFFFu;
    unsigned long long lmax = 0;
    for (int j = blockIdx.x * 256 + tid; j < N_HID; j += gridDim.x * 256) {
        float v = g_hidden[j];
        lsum += __double2ll_rn((double)v * FP_SCALE);
        unsigned k = fkey(v);
        lmin = min(lmin, k);
        lmax = max(lmax, ((unsigned long long)k << 32) | (unsigned)j);
    }
    __shared__ long long ss[256];
    __shared__ unsigned int smn[256];
    __shared__ unsigned long long smx[256];
    ss[tid] = lsum; smn[tid] = lmin; smx[tid] = lmax;
    __syncthreads();
    for (int o = 128; o > 0; o >>= 1) {
        if (tid < o) {
            ss[tid] += ss[tid + o];
            smn[tid] = min(smn[tid], smn[tid + o]);
            smx[tid] = max(smx[tid], smx[tid + o]);
        }
        __syncthreads();
    }
    __shared__ int s_last;
    if (tid == 0) {
        atomicAdd(&gh_sum, (unsigned long long)ss[0]);
        atomicMin(&gh_minb, smn[0]);
        atomicMax(&gh_maxp, smx[0]);
        __threadfence();
        unsigned t = atomicAdd(&g_ticket, 1u);
        s_last = (t == gridDim.x - 1) ? 1 : 0;
    }
    __syncthreads();
    if (!s_last) return;

    // ---- final layer-2 epilogue (only the last-finishing block runs this) ----
    const float Zsum = (float)((double)(long long)(*(volatile unsigned long long*)&gh_sum)
                               * (1.0 / FP_SCALE));
    const float zmin = fdec(*(volatile unsigned int*)&gh_minb);
    const unsigned long long p = *(volatile unsigned long long*)&gh_maxp;
    const float zmax = fdec((unsigned)(p >> 32));
    const int jlast = (int)(unsigned)p;

    for (int r = tid; r < N_OUT; r += 256) {
        const float Wsum = g_w2sum[r];
        const float tmp = Wsum * Zsum / (Wsum - 1.f);
        float result = INFINITY;
        if (Wsum > 1.f) {
            if (zmin <= tmp) {
                float Wc = Wsum - W2[(size_t)r * NIN + jlast];
                float Zc = Zsum - zmax;
                result = Wc * Zc / (Wc - 1.f);
            }
        } else {
            // rare general path: serial per-thread row scan (never taken here)
            int cnt = 0; float sle = 0.f, wle = 0.f, m = -INFINITY; int jm = -1;
            for (int j = 0; j < NIN; ++j) {
                float zj = g_hidden[j];
                if (zj <= tmp) {
                    cnt++; sle += zj; wle += W2[(size_t)r * NIN + j];
                    if (zj > m || (zj == m && j > jm)) { m = zj; jm = j; }
                }
            }
            if (cnt == NIN) {
                // inf
            } else if (cnt == 0) {
                float Wc = Wsum - W2[(size_t)r * NIN + jlast];
                float Zc = Zsum - zmax;
                result = Wc * Zc / (Wc - 1.f);
            } else {
                int k = cnt - 1;
                if (k != 0) {
                    float Zc = sle - m;
                    float Wc = wle - W2[(size_t)r * NIN + jm];
                    result = Wc * Zc / (Wc - 1.f);
                }
            }
        }
        out[r] = result;
    }
}

extern "C" void kernel_launch(void* const* d_in, const int* in_sizes, int n_in,
                              void* d_out, int out_size)
{
    const float* x  = (const float*)d_in[0];
    const float* W1 = (const float*)d_in[1];
    const float* W2 = (const float*)d_in[2];
    float* out = (float*)d_out;

    init_kernel<<<1, 1>>>();
    statsx_kernel<<<32, 256>>>(x);
    big_kernel<<<N_HID + N_OUT, 256>>>(W1, W2);
    statsh_final_kernel<<<16, 256>>>(W2, out);
}